// round 7
// baseline (speedup 1.0000x reference)
#include <cuda_runtime.h>
#include <math.h>

// ---------------------------------------------------------------------------
// PolicyLoss fused single kernel, v7.
//  - v6 structure, with:
//    * tid0-only __threadfence() release (was per-thread MEMBAR.GL)
//    * transposed policy partials for coalesced finalize fan-in
// ---------------------------------------------------------------------------

#define NCLS   100
#define BATCH  2048
#define NPAIR  1024
#define OCH    9

#define POLICY_BLOCKS 32
#define LOGIT_BLOCKS  256
#define GRID_BLOCKS   (POLICY_BLOCKS + LOGIT_BLOCKS)
#define TPB           256

// policy partial record layout
#define F_DIFF  0     // 9 ch x {SD, SD2, SE, SE2} -> 0..35
#define F_DIAG  36
#define F_SXB   37    // c=1..8 -> 37+(c-1)
#define F_SXB2  45    // c=2..8 -> 45+(c-2)
#define F_SYA   52    // c=1..8
#define F_SYA2  60    // c=2..8
#define F_NSTAT 67
#define F_CNT1  67    // [8][10]
#define F_CNT2  147
#define F_HA    227
#define F_HB    307
#define F_SIZE  387

__device__ float    g_ce[BATCH];
__device__ float    g_kl[BATCH];
__device__ float    g_ppT[F_SIZE][POLICY_BLOCKS];   // transposed: [stat][block]
__device__ unsigned g_ticket = 0;

__device__ __forceinline__ float warp_sum(float v) {
    #pragma unroll
    for (int o = 16; o; o >>= 1) v += __shfl_xor_sync(0xffffffffu, v, o);
    return v;
}

// sum over the 4 distinct values held (8x-replicated) in lane groups of 4
__device__ __forceinline__ float quad_sum(float v) {
    v += __shfl_xor_sync(0xffffffffu, v, 1);
    v += __shfl_xor_sync(0xffffffffu, v, 2);
    return v;
}

__global__ void __launch_bounds__(TPB)
fused_kernel(const float* __restrict__ slog,
             const float* __restrict__ tlog,
             const float* __restrict__ sp,
             const float* __restrict__ tp,
             const float* __restrict__ W1,
             const float* __restrict__ bias1,
             const float* __restrict__ W2,
             const float* __restrict__ bias2,
             const int*   __restrict__ targets,
             float* __restrict__ out) {
    __shared__ __align__(16) float sW[2 * OCH * 128];   // W2 | W1 (policy only)
    __shared__ float sStat[8 * F_NSTAT];                // per-warp stat slices
    __shared__ float sHist[320];                        // cnt1|cnt2|hA|hB
    __shared__ float sAcc[F_SIZE];                      // finalize scratch
    __shared__ float sRed[16];                          // finalize ce/kl partials
    __shared__ float sFin[8];
    __shared__ float b1s[OCH], b2s[OCH];
    __shared__ unsigned is_last;

    const int tid  = threadIdx.x;
    const int lane = tid & 31;
    const int warp = tid >> 5;
    const int bid  = blockIdx.x;

    if (bid < POLICY_BLOCKS) {
        // ----------------- policy: 8 threads per pair ----------------------
        {   // stage W2|W1 into smem with float4
            const float4* w2v = (const float4*)W2;
            const float4* w1v = (const float4*)W1;
            float4* d = (float4*)sW;
            for (int idx = tid; idx < (OCH * 128) / 4; idx += TPB) {
                d[idx]                   = w2v[idx];
                d[(OCH * 128) / 4 + idx] = w1v[idx];
            }
        }
        for (int idx = tid; idx < 320; idx += TPB) sHist[idx] = 0.f;
        __syncthreads();

        const int e = lane >> 2;                          // eighth 0..7
        const int i = bid * 32 + warp * 4 + (lane & 3);   // pair 0..1023
        const int fbase = e * 8;

        const float4* spA = (const float4*)(sp + (2 * i)     * 64 + fbase);
        const float4* spB = (const float4*)(sp + (2 * i + 1) * 64 + fbase);
        const float4* tpA = (const float4*)(tp + (2 * i)     * 64 + fbase);
        const float4* tpB = (const float4*)(tp + (2 * i + 1) * 64 + fbase);

        float sA[OCH], sB[OCH], tA[OCH], tB[OCH];
        #pragma unroll
        for (int k = 0; k < OCH; k++) { sA[k] = sB[k] = tA[k] = tB[k] = 0.f; }

        #pragma unroll
        for (int v = 0; v < 2; v++) {
            float4 a = spA[v], b = spB[v], c = tpA[v], d4 = tpB[v];
            int f = fbase + 4 * v;
            #pragma unroll
            for (int k = 0; k < OCH; k++) {
                float4 w2a = *(const float4*)&sW[k * 128 + f];
                float4 w2b = *(const float4*)&sW[k * 128 + 64 + f];
                float4 w1a = *(const float4*)&sW[OCH * 128 + k * 128 + f];
                float4 w1b = *(const float4*)&sW[OCH * 128 + k * 128 + 64 + f];
                sA[k] += a.x*w2a.x + a.y*w2a.y + a.z*w2a.z + a.w*w2a.w;
                sB[k] += b.x*w2b.x + b.y*w2b.y + b.z*w2b.z + b.w*w2b.w;
                tA[k] += c.x*w1a.x + c.y*w1a.y + c.z*w1a.z + c.w*w1a.w;
                tB[k] += d4.x*w1b.x + d4.y*w1b.y + d4.z*w1b.z + d4.w*w1b.w;
            }
        }
        // combine eighths: xor 4, 8, 16 -> all lanes hold full pair sums
        #pragma unroll
        for (int k = 0; k < OCH; k++) {
            #pragma unroll
            for (int o = 4; o <= 16; o <<= 1) {
                sA[k] += __shfl_xor_sync(0xffffffffu, sA[k], o);
                sB[k] += __shfl_xor_sync(0xffffffffu, sB[k], o);
                tA[k] += __shfl_xor_sync(0xffffffffu, tA[k], o);
                tB[k] += __shfl_xor_sync(0xffffffffu, tB[k], o);
            }
        }

        // 2-shfl reduction over the 4 distinct pairs in this warp
        #define WST(j, val) { float r_ = quad_sum(val); \
                              if (lane == 0) sStat[warp * F_NSTAT + (j)] = r_; }
        #pragma unroll
        for (int k = 0; k < OCH; k++) {
            float d = sB[k] - tB[k];
            float ev = sA[k] - tA[k];
            WST(F_DIFF + 4 * k + 0, d);
            WST(F_DIFF + 4 * k + 1, d * d);
            WST(F_DIFF + 4 * k + 2, ev);
            WST(F_DIFF + 4 * k + 3, ev * ev);
        }
        WST(F_DIAG, sB[0] + sA[0]);
        #pragma unroll
        for (int c = 1; c < OCH; c++) {
            WST(F_SXB + (c - 1), sB[c]);
            WST(F_SYA + (c - 1), sA[c]);
            if (c >= 2) {
                WST(F_SXB2 + (c - 2), sB[c] * sB[c]);
                WST(F_SYA2 + (c - 2), sA[c] * sA[c]);
            }
        }
        #undef WST

        // channel-split histograms: group e owns channel c = e+1
        {
            float myA = 0.f, myB = 0.f;
            #pragma unroll
            for (int c = 1; c < OCH; c++) {
                if (e == c - 1) { myA = sA[c]; myB = sB[c]; }
            }
            int v1 = targets[(2 * i)     * 8 + e];
            int v2 = targets[(2 * i + 1) * 8 + e];
            int off = e * 10;
            atomicAdd(&sHist[off + v1],       1.0f);     // cnt1
            atomicAdd(&sHist[160 + off + v1], myA);      // hA
            atomicAdd(&sHist[80 + off + v2],  1.0f);     // cnt2
            atomicAdd(&sHist[240 + off + v2], myB);      // hB
        }
        __syncthreads();

        // block combine -> transposed global partials
        for (int j = tid; j < F_NSTAT; j += TPB) {
            float s = 0.f;
            #pragma unroll
            for (int w = 0; w < 8; w++) s += sStat[w * F_NSTAT + j];
            g_ppT[j][bid] = s;
        }
        for (int j = tid; j < 320; j += TPB) g_ppT[F_NSTAT + j][bid] = sHist[j];
    } else {
        // ----------------- logits CE + KL: 1 row per warp, no-max softmax --
        const int lb  = bid - POLICY_BLOCKS;          // 0..255
        const int row = lb * 8 + warp;
        const float4* s4 = (const float4*)(slog + row * NCLS);
        const float4* t4 = (const float4*)(tlog + row * NCLS);
        const int label = targets[row * 8];           // warp-uniform

        float se = 0.f, se4 = 0.f, st = 0.f, klb = 0.f;
        float svv[4];
        bool act = (lane < 25);
        if (act) {
            float4 sv = s4[lane];
            float4 tv = t4[lane];
            float tvv[4];
            svv[0] = sv.x; svv[1] = sv.y; svv[2] = sv.z; svv[3] = sv.w;
            tvv[0] = tv.x; tvv[1] = tv.y; tvv[2] = tv.z; tvv[3] = tv.w;
            #pragma unroll
            for (int j = 0; j < 4; j++) {
                se  += __expf(svv[j]);
                se4 += __expf(svv[j] * 0.25f);
                float e4 = __expf(tvv[j] * 0.25f);
                st  += e4;
                klb += e4 * (0.25f * (tvv[j] - svv[j]));
            }
        } else {
            svv[0]=svv[1]=svv[2]=svv[3]=0.f;
        }
        // label pick via single shfl broadcast (label uniform across warp)
        int jsel = label & 3;
        float cand = (jsel == 0) ? svv[0] : (jsel == 1) ? svv[1]
                   : (jsel == 2) ? svv[2] : svv[3];
        float slabel = __shfl_sync(0xffffffffu, cand, label >> 2);

        se  = warp_sum(se);
        se4 = warp_sum(se4);
        st  = warp_sum(st);
        klb = warp_sum(klb);

        float ce = __logf(se) - slabel;
        float kl = klb / st + __logf(se4) - __logf(st);

        if (lane == 0) { g_ce[row] = ce; g_kl[row] = kl; }
    }

    // ----------------- last-block-done finalize ---------------------------
    // bar.sync orders all block threads' writes to tid0 (CTA scope);
    // tid0's fence.gl promotes them GPU-wide (cumulativity), then ticket.
    __syncthreads();
    if (tid == 0) {
        __threadfence();
        unsigned t = atomicAdd(&g_ticket, 1u);
        is_last = (t == GRID_BLOCKS - 1) ? 1u : 0u;
        if (is_last) {
            g_ticket = 0;         // reset for next graph replay
            __threadfence();      // acquire-side ordering for the reads below
        }
    }
    __syncthreads();
    if (!is_last) return;

    // ---- stage 1: parallel gather --------------------------------------
    if (tid < OCH) { b1s[tid] = bias1[tid]; b2s[tid] = bias2[tid]; }

    {   // ce/kl: 8 rows per thread (2 float4 loads per array)
        const float4* c4 = (const float4*)g_ce;
        const float4* k4 = (const float4*)g_kl;
        float4 a0 = c4[tid * 2], a1 = c4[tid * 2 + 1];
        float4 b0 = k4[tid * 2], b1 = k4[tid * 2 + 1];
        float ce_p = (a0.x + a0.y) + (a0.z + a0.w) + (a1.x + a1.y) + (a1.z + a1.w);
        float kl_p = (b0.x + b0.y) + (b0.z + b0.w) + (b1.x + b1.y) + (b1.z + b1.w);
        ce_p = warp_sum(ce_p);
        kl_p = warp_sum(kl_p);
        if (lane == 0) { sRed[warp] = ce_p; sRed[8 + warp] = kl_p; }
    }

    // policy partials fan-in: 32 contiguous floats per stat (coalesced)
    for (int idx = tid; idx < F_SIZE; idx += TPB) {
        const float4* r = (const float4*)g_ppT[idx];
        float s = 0.f;
        #pragma unroll
        for (int q = 0; q < POLICY_BLOCKS / 4; q++) {
            float4 v = r[q];
            s += (v.x + v.y) + (v.z + v.w);
        }
        sAcc[idx] = s;
    }
    __syncthreads();

    // ---- stage 2: 113 additive units + block reduce --------------------
    const float N = (float)NPAIR;
    const float M = N * N;
    float val = 0.f;

    if (tid < 8) {
        val = sRed[tid] * (1.0f / (float)BATCH);                       // ce
    } else if (tid < 16) {
        val = sRed[tid] * (16.0f / ((float)BATCH * (float)NCLS));      // kl
    } else if (tid < 25) {
        int k = tid - 16;                                              // klp
        float db  = b2s[k] - b1s[k];
        float SDr = sAcc[F_DIFF + 4 * k + 0];
        float SD2 = sAcc[F_DIFF + 4 * k + 1];
        float SEr = sAcc[F_DIFF + 4 * k + 2];
        float SE2 = sAcc[F_DIFF + 4 * k + 3];
        float Sd  = SDr + N * db;
        float Sd2 = SD2 + 2.f * db * SDr + N * db * db;
        float grid = N * Sd2 + N * SE2 + 2.f * Sd * SEr;
        float wk = (k == 0) ? (1.f / M) : (k == 1) ? (0.5f / M)
                                        : (0.001f / (7.f * M));
        val = grid * wk;
    } else if (tid == 25) {
        val = -(sAcc[F_DIAG] + N * b2s[0]) / M;                        // termI
    } else if (tid >= 32 && tid < 42) {
        int v = tid - 32;                                              // termC
        float c1 = sAcc[F_CNT1 + v];
        float c2 = sAcc[F_CNT2 + v];
        float hA = sAcc[F_HA + v];
        float hB = sAcc[F_HB + v];
        val = (-0.5f / M) * (c1 * hB + c2 * hA + c1 * c2 * b2s[1]);
    } else if (tid >= 48 && tid < 118) {
        int u = tid - 48;                                              // termP hist
        int c = 2 + u / 10;
        int v = u - (c - 2) * 10;
        int off = (c - 1) * 10;
        float b  = b2s[c];
        float c1 = sAcc[F_CNT1 + off + v];
        float c2 = sAcc[F_CNT2 + off + v];
        float hA = sAcc[F_HA + off + v];
        float hB = sAcc[F_HB + off + v];
        val = (-0.004f / (7.f * M)) * (c1 * (hB + b * c2) + c2 * hA);
    } else if (tid >= 120 && tid < 127) {
        int c = 2 + (tid - 120);                                       // termP mom.
        float b    = b2s[c];
        float SxB  = sAcc[F_SXB  + (c - 1)];
        float SxB2 = sAcc[F_SXB2 + (c - 2)];
        float SyA  = sAcc[F_SYA  + (c - 1)];
        float SyA2 = sAcc[F_SYA2 + (c - 2)];
        float Sx   = SxB + N * b;
        float Sx2  = SxB2 + 2.f * b * SxB + N * b * b;
        float Sw2  = N * Sx2 + N * SyA2 + 2.f * Sx * SyA;
        val = (0.001f / (7.f * M)) * (Sw2 + 2.f * N * (Sx + SyA) + M);
    }

    val = warp_sum(val);
    if (lane == 0) sFin[warp] = val;
    __syncthreads();
    if (tid == 0) {
        float o = 0.f;
        #pragma unroll
        for (int w = 0; w < 8; w++) o += sFin[w];
        out[0] = o;
    }
}

// ---------------------------------------------------------------------------
extern "C" void kernel_launch(void* const* d_in, const int* in_sizes, int n_in,
                              void* d_out, int out_size) {
    const float* student_logits = (const float*)d_in[0];
    const float* teacher_logits = (const float*)d_in[1];
    const float* student_policy = (const float*)d_in[2];
    const float* teacher_policy = (const float*)d_in[3];
    const float* W1             = (const float*)d_in[4];
    const float* bias1          = (const float*)d_in[5];
    const float* W2             = (const float*)d_in[6];
    const float* bias2          = (const float*)d_in[7];
    const int*   targets        = (const int*)d_in[8];
    float* out = (float*)d_out;

    fused_kernel<<<GRID_BLOCKS, TPB>>>(student_logits, teacher_logits,
                                       student_policy, teacher_policy,
                                       W1, bias1, W2, bias2, targets, out);
}